// round 1
// baseline (speedup 1.0000x reference)
#include <cuda_runtime.h>
#include <math.h>

#define T_STEPS 16
#define IN_DIM  12288
#define H1 256
#define H2 512
#define BATCH 128
#define M_ROWS (T_STEPS * BATCH)   // 2048

// ---------------- scratch (no cudaMalloc allowed) ----------------
__device__ float g_pre1[M_ROWS * 4 * H1];   // 8 MB
__device__ float g_y1  [M_ROWS * H1];       // 2 MB
__device__ float g_pre2[M_ROWS * 4 * H2];   // 16 MB
__device__ float g_h[2][BATCH * H2];
__device__ float g_c[2][BATCH * H2];

// ---------------- utility ----------------
__global__ void zero_hc(float* __restrict__ h, float* __restrict__ c, int n) {
    int i = blockIdx.x * blockDim.x + threadIdx.x;
    if (i < n) { h[i] = 0.f; c[i] = 0.f; }
}

// ---------------- big GEMM: C[M,N] = A[M,K] @ W[N,K]^T + bias[N] ----------------
// 128x128 tile, Kc=16, 256 threads, 8x8 microtile. M,N mult of 128, K mult of 16.
__global__ __launch_bounds__(256) void gemm_bias128(
    const float* __restrict__ A, const float* __restrict__ W,
    const float* __restrict__ bias, float* __restrict__ C,
    int M, int N, int K)
{
    __shared__ float As[16][129];
    __shared__ float Bs[16][129];

    const int tid = threadIdx.x;
    const int tx = tid & 15;
    const int ty = tid >> 4;
    const int m0 = blockIdx.y * 128;
    const int n0 = blockIdx.x * 128;

    float acc[8][8];
    #pragma unroll
    for (int i = 0; i < 8; ++i)
        #pragma unroll
        for (int j = 0; j < 8; ++j) acc[i][j] = 0.f;

    for (int k0 = 0; k0 < K; k0 += 16) {
        #pragma unroll
        for (int i = tid; i < 128 * 16; i += 256) {
            int m = i >> 4, k = i & 15;
            As[k][m] = A[(size_t)(m0 + m) * K + k0 + k];
        }
        #pragma unroll
        for (int i = tid; i < 128 * 16; i += 256) {
            int n = i >> 4, k = i & 15;
            Bs[k][n] = W[(size_t)(n0 + n) * K + k0 + k];
        }
        __syncthreads();

        #pragma unroll
        for (int kc = 0; kc < 16; ++kc) {
            float a[8], b[8];
            #pragma unroll
            for (int i = 0; i < 8; ++i) a[i] = As[kc][ty + 16 * i];
            #pragma unroll
            for (int j = 0; j < 8; ++j) b[j] = Bs[kc][tx + 16 * j];
            #pragma unroll
            for (int i = 0; i < 8; ++i)
                #pragma unroll
                for (int j = 0; j < 8; ++j) acc[i][j] += a[i] * b[j];
        }
        __syncthreads();
    }

    #pragma unroll
    for (int i = 0; i < 8; ++i) {
        int m = m0 + ty + 16 * i;
        #pragma unroll
        for (int j = 0; j < 8; ++j) {
            int n = n0 + tx + 16 * j;
            C[(size_t)m * N + n] = acc[i][j] + bias[n];
        }
    }
}

// ---------------- fused LSTM step ----------------
// gates[b, g*H+j] = pre[b, g*H+j] + sum_k h_in[b,k] * Whh[g*H+j, k]
// tile: 16 batches x 32 j's x 4 gates. 256 threads, each 2 batches x 4 gates.
template<int H>
__global__ __launch_bounds__(256) void lstm_step(
    const float* __restrict__ pre_t,   // [B, 4H]
    const float* __restrict__ h_in,    // [B, H]
    const float* __restrict__ c_in,    // [B, H]
    const float* __restrict__ Whh,     // [4H, H]
    float* __restrict__ h_out,
    float* __restrict__ c_out,
    float* __restrict__ y_out)         // [B, H]
{
    __shared__ float Hs[16][33];
    __shared__ float Ws[4][32][33];

    const int tid = threadIdx.x;
    const int tx = tid & 31;   // local j
    const int ty = tid >> 5;   // 0..7
    const int b0 = blockIdx.x * 16;
    const int j0 = blockIdx.y * 32;

    float acc[4][2] = {};

    for (int k0 = 0; k0 < H; k0 += 32) {
        for (int i = tid; i < 16 * 32; i += 256) {
            int bb = i >> 5, kk = i & 31;
            Hs[bb][kk] = h_in[(b0 + bb) * H + k0 + kk];
        }
        for (int i = tid; i < 4 * 32 * 32; i += 256) {
            int g  = i >> 10;
            int j  = (i >> 5) & 31;
            int kk = i & 31;
            Ws[g][kk][j] = Whh[(size_t)(g * H + j0 + j) * H + k0 + kk];
        }
        __syncthreads();

        #pragma unroll
        for (int kc = 0; kc < 32; ++kc) {
            float hv0 = Hs[ty][kc];
            float hv1 = Hs[ty + 8][kc];
            float w0 = Ws[0][kc][tx];
            float w1 = Ws[1][kc][tx];
            float w2 = Ws[2][kc][tx];
            float w3 = Ws[3][kc][tx];
            acc[0][0] += w0 * hv0;  acc[0][1] += w0 * hv1;
            acc[1][0] += w1 * hv0;  acc[1][1] += w1 * hv1;
            acc[2][0] += w2 * hv0;  acc[2][1] += w2 * hv1;
            acc[3][0] += w3 * hv0;  acc[3][1] += w3 * hv1;
        }
        __syncthreads();
    }

    #pragma unroll
    for (int bb = 0; bb < 2; ++bb) {
        int b = b0 + ty + bb * 8;
        int j = j0 + tx;
        const float* p = pre_t + (size_t)b * 4 * H;
        float ig = acc[0][bb] + p[j];
        float fg = acc[1][bb] + p[H + j];
        float gg = acc[2][bb] + p[2 * H + j];
        float og = acc[3][bb] + p[3 * H + j];
        float si = 1.f / (1.f + expf(-ig));
        float sf = 1.f / (1.f + expf(-fg));
        float so = 1.f / (1.f + expf(-og));
        float c2 = sf * c_in[b * H + j] + si * tanhf(gg);
        float h2 = so * tanhf(c2);
        c_out[b * H + j] = c2;
        h_out[b * H + j] = h2;
        y_out[b * H + j] = h2;
    }
}

// ---------------- launch ----------------
extern "C" void kernel_launch(void* const* d_in, const int* in_sizes, int n_in,
                              void* d_out, int out_size)
{
    const float* inp  = (const float*)d_in[0];   // [B,T,IN] flat == [T*B, IN] per ref reshape
    const float* Wih1 = (const float*)d_in[1];   // [4H1, IN]
    const float* Whh1 = (const float*)d_in[2];   // [4H1, H1]
    const float* b1   = (const float*)d_in[3];   // [4H1]
    const float* Wih2 = (const float*)d_in[4];   // [4H2, H1]
    const float* Whh2 = (const float*)d_in[5];   // [4H2, H2]
    const float* b2   = (const float*)d_in[6];   // [4H2]
    float* out = (float*)d_out;                  // flat [T,B,H2] == [B, T*H2] reshape

    float *pre1, *y1, *pre2, *hbase, *cbase;
    cudaGetSymbolAddress((void**)&pre1,  g_pre1);
    cudaGetSymbolAddress((void**)&y1,    g_y1);
    cudaGetSymbolAddress((void**)&pre2,  g_pre2);
    cudaGetSymbolAddress((void**)&hbase, g_h);
    cudaGetSymbolAddress((void**)&cbase, g_c);
    float* hb[2] = { hbase, hbase + BATCH * H2 };
    float* cb[2] = { cbase, cbase + BATCH * H2 };

    // ---- layer 1 ----
    // pre1[T*B, 4H1] = inp @ Wih1^T + b1
    gemm_bias128<<<dim3(4 * H1 / 128, M_ROWS / 128), 256>>>(
        inp, Wih1, b1, pre1, M_ROWS, 4 * H1, IN_DIM);

    zero_hc<<<(BATCH * H1 + 255) / 256, 256>>>(hb[0], cb[0], BATCH * H1);

    int p = 0;
    for (int t = 0; t < T_STEPS; ++t) {
        lstm_step<H1><<<dim3(BATCH / 16, H1 / 32), 256>>>(
            pre1 + (size_t)t * BATCH * 4 * H1,
            hb[p], cb[p], Whh1,
            hb[1 - p], cb[1 - p],
            y1 + (size_t)t * BATCH * H1);
        p ^= 1;
    }

    // ---- layer 2 ----
    // pre2[T*B, 4H2] = y1 @ Wih2^T + b2
    gemm_bias128<<<dim3(4 * H2 / 128, M_ROWS / 128), 256>>>(
        y1, Wih2, b2, pre2, M_ROWS, 4 * H2, H1);

    zero_hc<<<(BATCH * H2 + 255) / 256, 256>>>(hb[0], cb[0], BATCH * H2);

    p = 0;
    for (int t = 0; t < T_STEPS; ++t) {
        lstm_step<H2><<<dim3(BATCH / 16, H2 / 32), 256>>>(
            pre2 + (size_t)t * BATCH * 4 * H2,
            hb[p], cb[p], Whh2,
            hb[1 - p], cb[1 - p],
            out + (size_t)t * BATCH * H2);
        p ^= 1;
    }
}

// round 2
// speedup vs baseline: 2.1662x; 2.1662x over previous
#include <cuda_runtime.h>
#include <math.h>

#define T_STEPS 16
#define IN_DIM  12288
#define H1 256
#define H2 512
#define BATCH 128
#define M_ROWS (T_STEPS * BATCH)   // 2048
#define NBLK 128                   // persistent grid (must all be co-resident; <=148 SMs)

// ---------------- scratch (no cudaMalloc allowed) ----------------
__device__ float g_pre1[M_ROWS * 4 * H1];   // 8 MB
__device__ float g_y1  [M_ROWS * H1];       // 2 MB
__device__ float g_pre2[M_ROWS * 4 * H2];   // 16 MB
__device__ float g_h1[2][H1 * BATCH];       // k-major h ping-pong, layer 1
__device__ float g_h2[2][H2 * BATCH];       // k-major h ping-pong, layer 2
__device__ unsigned g_cnt1, g_gen1, g_cnt2, g_gen2;

// ---------------- grid barrier (all NBLK blocks co-resident) ----------------
__device__ __forceinline__ void grid_sync(unsigned* cnt, unsigned* gen, unsigned& local) {
    __syncthreads();
    if (threadIdx.x == 0) {
        __threadfence();                       // release: my stores visible
        if (atomicAdd(cnt, 1u) == NBLK - 1u) {
            atomicExch(cnt, 0u);
            __threadfence();
            atomicAdd(gen, 1u);                // release all
        } else {
            while (atomicAdd(gen, 0u) == local) { }
        }
        __threadfence();                       // acquire: remote stores visible
    }
    __syncthreads();
    local++;
}

// ---------------- big GEMM: C[M,N] = A[M,K] @ W[N,K]^T + bias[N] ----------------
__global__ __launch_bounds__(256) void gemm_bias128(
    const float* __restrict__ A, const float* __restrict__ W,
    const float* __restrict__ bias, float* __restrict__ C,
    int M, int N, int K)
{
    __shared__ float As[16][129];
    __shared__ float Bs[16][129];

    const int tid = threadIdx.x;
    const int tx = tid & 15;
    const int ty = tid >> 4;
    const int m0 = blockIdx.y * 128;
    const int n0 = blockIdx.x * 128;

    float acc[8][8];
    #pragma unroll
    for (int i = 0; i < 8; ++i)
        #pragma unroll
        for (int j = 0; j < 8; ++j) acc[i][j] = 0.f;

    for (int k0 = 0; k0 < K; k0 += 16) {
        #pragma unroll
        for (int i = tid; i < 128 * 16; i += 256) {
            int m = i >> 4, k = i & 15;
            As[k][m] = A[(size_t)(m0 + m) * K + k0 + k];
        }
        #pragma unroll
        for (int i = tid; i < 128 * 16; i += 256) {
            int n = i >> 4, k = i & 15;
            Bs[k][n] = W[(size_t)(n0 + n) * K + k0 + k];
        }
        __syncthreads();

        #pragma unroll
        for (int kc = 0; kc < 16; ++kc) {
            float a[8], b[8];
            #pragma unroll
            for (int i = 0; i < 8; ++i) a[i] = As[kc][ty + 16 * i];
            #pragma unroll
            for (int j = 0; j < 8; ++j) b[j] = Bs[kc][tx + 16 * j];
            #pragma unroll
            for (int i = 0; i < 8; ++i)
                #pragma unroll
                for (int j = 0; j < 8; ++j) acc[i][j] += a[i] * b[j];
        }
        __syncthreads();
    }

    #pragma unroll
    for (int i = 0; i < 8; ++i) {
        int m = m0 + ty + 16 * i;
        #pragma unroll
        for (int j = 0; j < 8; ++j) {
            int n = n0 + tx + 16 * j;
            C[(size_t)m * N + n] = acc[i][j] + bias[n];
        }
    }
}

__device__ __forceinline__ float sigf(float x) { return 1.f / (1.f + expf(-x)); }

// ---------------- persistent LSTM layer 1 (H=256) ----------------
// 128 blocks x 256 threads. Block owns h-cols j0=bid*2..+1 (8 Whh rows).
// thread: b = tid&127, jj = tid>>7 (one h-col, 4 gates). c in registers.
__global__ __launch_bounds__(256) void lstm_layer1(
    const float* __restrict__ pre,    // [T*B][4*H1]
    const float* __restrict__ Whh,    // [4*H1][H1]
    float* __restrict__ y1)           // [T*B][H1]
{
    extern __shared__ float smem[];
    float* Wst = smem;                 // [H1][2][4] = 2048 floats
    float* hs  = smem + H1 * 8;        // [64][128]  = 8192 floats

    const int tid = threadIdx.x;
    const int bid = blockIdx.x;
    const int b   = tid & 127;
    const int jj  = tid >> 7;          // 0..1
    const int j   = bid * 2 + jj;

    // stage Whh slice, transposed: Wst[k*8 + jj2*4 + g]
    #pragma unroll
    for (int r = 0; r < 8; ++r) {
        int jj2 = r >> 2, g = r & 3;
        const float* wrow = Whh + ((size_t)(g * H1 + bid * 2 + jj2)) * H1;
        for (int k = tid; k < H1; k += 256) Wst[k * 8 + jj2 * 4 + g] = wrow[k];
    }

    __shared__ unsigned s_gen;
    if (tid == 0) s_gen = atomicAdd(&g_gen1, 0u);
    __syncthreads();
    unsigned local = s_gen;

    float c0 = 0.f;

    for (int t = 0; t < T_STEPS; ++t) {
        float a0 = 0.f, a1 = 0.f, a2 = 0.f, a3 = 0.f;
        if (t > 0) {
            const float* hprev = g_h1[(t - 1) & 1];
            for (int k0 = 0; k0 < H1; k0 += 64) {
                const float4* src = (const float4*)(hprev + k0 * BATCH);
                float4* dst = (float4*)hs;
                #pragma unroll
                for (int i = tid; i < 64 * BATCH / 4; i += 256) dst[i] = src[i];
                __syncthreads();
                #pragma unroll 8
                for (int kk = 0; kk < 64; ++kk) {
                    float hv = hs[kk * BATCH + b];
                    float4 w = *(const float4*)(Wst + (size_t)(k0 + kk) * 8 + jj * 4);
                    a0 += w.x * hv; a1 += w.y * hv; a2 += w.z * hv; a3 += w.w * hv;
                }
                __syncthreads();
            }
        }
        const float* p = pre + ((size_t)t * BATCH + b) * (4 * H1);
        float ig = a0 + p[j];
        float fg = a1 + p[H1 + j];
        float gg = a2 + p[2 * H1 + j];
        float og = a3 + p[3 * H1 + j];
        c0 = sigf(fg) * c0 + sigf(ig) * tanhf(gg);
        float h2 = sigf(og) * tanhf(c0);
        y1[((size_t)t * BATCH + b) * H1 + j] = h2;
        if (t < T_STEPS - 1) {
            g_h1[t & 1][j * BATCH + b] = h2;
            grid_sync(&g_cnt1, &g_gen1, local);
        }
    }
}

// ---------------- persistent LSTM layer 2 (H=512) ----------------
// 128 blocks x 256 threads. Block owns h-cols j0=bid*4..+3 (16 Whh rows).
// thread: b = tid&127, jp = tid>>7 -> h-cols jp*2, jp*2+1 (8 gate accums).
__global__ __launch_bounds__(256) void lstm_layer2(
    const float* __restrict__ pre,    // [T*B][4*H2]
    const float* __restrict__ Whh,    // [4*H2][H2]
    float* __restrict__ out)          // [T*B][H2]
{
    extern __shared__ float smem[];
    float* Wst = smem;                 // [H2][4][4] = 8192 floats
    float* hs  = smem + H2 * 16;       // [64][128]  = 8192 floats

    const int tid = threadIdx.x;
    const int bid = blockIdx.x;
    const int b   = tid & 127;
    const int jp  = tid >> 7;          // 0..1

    // stage Whh slice, transposed: Wst[k*16 + jj*4 + g]
    #pragma unroll
    for (int r = 0; r < 16; ++r) {
        int jj = r >> 2, g = r & 3;
        const float* wrow = Whh + ((size_t)(g * H2 + bid * 4 + jj)) * H2;
        for (int k = tid; k < H2; k += 256) Wst[k * 16 + jj * 4 + g] = wrow[k];
    }

    __shared__ unsigned s_gen;
    if (tid == 0) s_gen = atomicAdd(&g_gen2, 0u);
    __syncthreads();
    unsigned local = s_gen;

    float c0 = 0.f, c1 = 0.f;

    for (int t = 0; t < T_STEPS; ++t) {
        float acc[8];
        #pragma unroll
        for (int i = 0; i < 8; ++i) acc[i] = 0.f;

        if (t > 0) {
            const float* hprev = g_h2[(t - 1) & 1];
            for (int k0 = 0; k0 < H2; k0 += 64) {
                const float4* src = (const float4*)(hprev + k0 * BATCH);
                float4* dst = (float4*)hs;
                #pragma unroll
                for (int i = tid; i < 64 * BATCH / 4; i += 256) dst[i] = src[i];
                __syncthreads();
                #pragma unroll 4
                for (int kk = 0; kk < 64; ++kk) {
                    float hv = hs[kk * BATCH + b];
                    const float* wp = Wst + (size_t)(k0 + kk) * 16 + jp * 8;
                    float4 wa = *(const float4*)(wp);
                    float4 wb = *(const float4*)(wp + 4);
                    acc[0] += wa.x * hv; acc[1] += wa.y * hv;
                    acc[2] += wa.z * hv; acc[3] += wa.w * hv;
                    acc[4] += wb.x * hv; acc[5] += wb.y * hv;
                    acc[6] += wb.z * hv; acc[7] += wb.w * hv;
                }
                __syncthreads();
            }
        }

        const float* p = pre + ((size_t)t * BATCH + b) * (4 * H2);
        #pragma unroll
        for (int u = 0; u < 2; ++u) {
            int j = bid * 4 + jp * 2 + u;
            float ig = acc[u * 4 + 0] + p[j];
            float fg = acc[u * 4 + 1] + p[H2 + j];
            float gg = acc[u * 4 + 2] + p[2 * H2 + j];
            float og = acc[u * 4 + 3] + p[3 * H2 + j];
            float c = (u == 0) ? c0 : c1;
            c = sigf(fg) * c + sigf(ig) * tanhf(gg);
            if (u == 0) c0 = c; else c1 = c;
            float h2 = sigf(og) * tanhf(c);
            out[((size_t)t * BATCH + b) * H2 + j] = h2;
            if (t < T_STEPS - 1) g_h2[t & 1][j * BATCH + b] = h2;
        }
        if (t < T_STEPS - 1) grid_sync(&g_cnt2, &g_gen2, local);
    }
}

// ---------------- launch ----------------
extern "C" void kernel_launch(void* const* d_in, const int* in_sizes, int n_in,
                              void* d_out, int out_size)
{
    const float* inp  = (const float*)d_in[0];
    const float* Wih1 = (const float*)d_in[1];
    const float* Whh1 = (const float*)d_in[2];
    const float* b1   = (const float*)d_in[3];
    const float* Wih2 = (const float*)d_in[4];
    const float* Whh2 = (const float*)d_in[5];
    const float* b2   = (const float*)d_in[6];
    float* out = (float*)d_out;

    float *pre1, *y1, *pre2;
    cudaGetSymbolAddress((void**)&pre1, g_pre1);
    cudaGetSymbolAddress((void**)&y1,   g_y1);
    cudaGetSymbolAddress((void**)&pre2, g_pre2);

    const int smem1 = (H1 * 8 + 64 * BATCH) * sizeof(float);   // 40 KB
    const int smem2 = (H2 * 16 + 64 * BATCH) * sizeof(float);  // 64 KB
    cudaFuncSetAttribute(lstm_layer2, cudaFuncAttributeMaxDynamicSharedMemorySize, smem2);

    // ---- layer 1 ----
    gemm_bias128<<<dim3(4 * H1 / 128, M_ROWS / 128), 256>>>(
        inp, Wih1, b1, pre1, M_ROWS, 4 * H1, IN_DIM);

    lstm_layer1<<<NBLK, 256, smem1>>>(pre1, Whh1, y1);

    // ---- layer 2 ----
    gemm_bias128<<<dim3(4 * H2 / 128, M_ROWS / 128), 256>>>(
        y1, Wih2, b2, pre2, M_ROWS, 4 * H2, H1);

    lstm_layer2<<<NBLK, 256, smem2>>>(pre2, Whh2, out);
}

// round 5
// speedup vs baseline: 3.6305x; 1.6760x over previous
#include <cuda_runtime.h>
#include <cuda_bf16.h>
#include <math.h>
#include <stdint.h>

#define T_STEPS 16
#define IN_DIM  12288
#define H1 256
#define H2 512
#define BATCH 128
#define M_ROWS (T_STEPS * BATCH)   // 2048
#define NBLK 128

// ---------------- scratch (no cudaMalloc allowed) ----------------
__device__ float g_pre1[M_ROWS * 4 * H1];            // 8 MB
__device__ float g_y1  [M_ROWS * H1];                // 2 MB
__device__ float g_pre2[M_ROWS * 4 * H2];            // 16 MB
__device__ float g_h1[2][H1 * BATCH];
__device__ float g_h2[2][H2 * BATCH];
__device__ unsigned g_cnt1, g_gen1, g_cnt2, g_gen2;

// split-bf16 operands, 3 segments along K:
//   A-side: [hi | lo | hi]   W-side: [hi | hi | lo]
// => A'.W'^T = Ahi.Whi + Alo.Whi + Ahi.Wlo  (error ~ Alo.Wlo ~ 2^-18)
__device__ __nv_bfloat16 g_A1s[M_ROWS * 3 * IN_DIM];     // 151 MB
__device__ __nv_bfloat16 g_W1s[4 * H1 * 3 * IN_DIM];     // 75 MB
__device__ __nv_bfloat16 g_y1s[M_ROWS * 3 * H1];         // 3 MB
__device__ __nv_bfloat16 g_W2s[4 * H2 * 3 * H1];         // 3 MB

// ---------------- fp32 -> split bf16 (3 segments along K) ----------------
// a_mode=1: [hi | lo | hi]  (activations)   a_mode=0: [hi | hi | lo]  (weights)
__global__ void split_bf16(const float* __restrict__ src, __nv_bfloat16* __restrict__ dst,
                           int K, int a_mode) {
    int r = blockIdx.y;
    int k = (blockIdx.x * blockDim.x + threadIdx.x) * 4;
    if (k >= K) return;
    float4 a = *(const float4*)(src + (size_t)r * K + k);
    __nv_bfloat16* d0 = dst + (size_t)r * 3 * K + k;          // hi
    __nv_bfloat16* d1 = d0 + K;                               // lo (A) / hi (W)
    __nv_bfloat16* d2 = d0 + 2 * K;                           // hi (A) / lo (W)
    float v[4] = {a.x, a.y, a.z, a.w};
    #pragma unroll
    for (int i = 0; i < 4; ++i) {
        __nv_bfloat16 hi = __float2bfloat16(v[i]);
        __nv_bfloat16 lo = __float2bfloat16(v[i] - __bfloat162float(hi));
        d0[i] = hi;
        if (a_mode) { d1[i] = lo; d2[i] = hi; }
        else        { d1[i] = hi; d2[i] = lo; }
    }
}

// ---------------- HMMA GEMM: C[M,N] = A[M,K2] @ W[N,K2]^T + bias ----------------
// 128x128 CTA tile, BK=32 bf16, 8 warps (4M x 2N), warp tile 32x64.
// mma.sync.m16n8k16 bf16; ldmatrix (non-trans for BOTH A and B — W rows are
// n-major with k contiguous, which IS the B fragment layout); pitch-40 smem
// (80 B rows, conflict-free ldmatrix); register-prefetch double buffer.
#define PITCH 40

__device__ __forceinline__ uint32_t smem_u32(const void* p) {
    uint32_t a;
    asm("{ .reg .u64 t; cvta.to.shared.u64 t, %1; cvt.u32.u64 %0, t; }" : "=r"(a) : "l"(p));
    return a;
}
__device__ __forceinline__ void ldsm_x4(uint32_t& r0, uint32_t& r1, uint32_t& r2, uint32_t& r3, uint32_t a) {
    asm volatile("ldmatrix.sync.aligned.m8n8.x4.shared.b16 {%0,%1,%2,%3}, [%4];"
                 : "=r"(r0), "=r"(r1), "=r"(r2), "=r"(r3) : "r"(a));
}
__device__ __forceinline__ void mma16816(float* c, const uint32_t* a, const uint32_t* b) {
    asm volatile(
        "mma.sync.aligned.m16n8k16.row.col.f32.bf16.bf16.f32 "
        "{%0,%1,%2,%3}, {%4,%5,%6,%7}, {%8,%9}, {%0,%1,%2,%3};"
        : "+f"(c[0]), "+f"(c[1]), "+f"(c[2]), "+f"(c[3])
        : "r"(a[0]), "r"(a[1]), "r"(a[2]), "r"(a[3]), "r"(b[0]), "r"(b[1]));
}

__global__ __launch_bounds__(256) void gemm_hmma(
    const __nv_bfloat16* __restrict__ A, const __nv_bfloat16* __restrict__ W,
    const float* __restrict__ bias, float* __restrict__ C, int N, int K2)
{
    __shared__ __nv_bfloat16 As[2][128 * PITCH];
    __shared__ __nv_bfloat16 Bs[2][128 * PITCH];

    const int tid = threadIdx.x;
    const int lane = tid & 31;
    const int wid = tid >> 5;
    const int moff = (wid >> 1) * 32;
    const int noff = (wid & 1) * 64;
    const int m0 = blockIdx.y * 128;
    const int n0 = blockIdx.x * 128;
    const int NT = K2 >> 5;

    const int r0g = tid >> 2, c0g = (tid & 3) * 8;
    const int r1g = r0g + 64;

    float acc[2][8][4];
    #pragma unroll
    for (int mt = 0; mt < 2; ++mt)
        #pragma unroll
        for (int nt = 0; nt < 8; ++nt)
            #pragma unroll
            for (int i = 0; i < 4; ++i) acc[mt][nt][i] = 0.f;

    uint4 ra0, ra1, rb0, rb1;
    const __nv_bfloat16* Ab = A + (size_t)m0 * K2;
    const __nv_bfloat16* Wb = W + (size_t)n0 * K2;

    // prologue: tile 0 -> regs -> smem[0]
    ra0 = *(const uint4*)(Ab + (size_t)r0g * K2 + c0g);
    ra1 = *(const uint4*)(Ab + (size_t)r1g * K2 + c0g);
    rb0 = *(const uint4*)(Wb + (size_t)r0g * K2 + c0g);
    rb1 = *(const uint4*)(Wb + (size_t)r1g * K2 + c0g);
    *(uint4*)&As[0][r0g * PITCH + c0g] = ra0;
    *(uint4*)&As[0][r1g * PITCH + c0g] = ra1;
    *(uint4*)&Bs[0][r0g * PITCH + c0g] = rb0;
    *(uint4*)&Bs[0][r1g * PITCH + c0g] = rb1;
    __syncthreads();

    const int lrow = lane & 15;
    const int lhalf = (lane >> 4) * 8;

    for (int kt = 0; kt < NT; ++kt) {
        const int cur = kt & 1;

        if (kt + 1 < NT) {
            const int k0 = (kt + 1) << 5;
            ra0 = *(const uint4*)(Ab + (size_t)r0g * K2 + k0 + c0g);
            ra1 = *(const uint4*)(Ab + (size_t)r1g * K2 + k0 + c0g);
            rb0 = *(const uint4*)(Wb + (size_t)r0g * K2 + k0 + c0g);
            rb1 = *(const uint4*)(Wb + (size_t)r1g * K2 + k0 + c0g);
        }

        const uint32_t sA = smem_u32(&As[cur][0]);
        const uint32_t sB = smem_u32(&Bs[cur][0]);

        #pragma unroll
        for (int ks = 0; ks < 32; ks += 16) {
            uint32_t af[2][4];
            #pragma unroll
            for (int mt = 0; mt < 2; ++mt) {
                uint32_t addr = sA + (uint32_t)((moff + mt * 16 + lrow) * PITCH + ks + lhalf) * 2u;
                ldsm_x4(af[mt][0], af[mt][1], af[mt][2], af[mt][3], addr);
            }
            uint32_t bf[8][2];
            #pragma unroll
            for (int nt2 = 0; nt2 < 4; ++nt2) {
                uint32_t t0, t1, t2, t3;
                uint32_t addr = sB + (uint32_t)((noff + nt2 * 16 + lrow) * PITCH + ks + lhalf) * 2u;
                ldsm_x4(t0, t1, t2, t3, addr);   // NON-trans: W rows are n, k contiguous
                bf[nt2 * 2 + 0][0] = t0; bf[nt2 * 2 + 0][1] = t2;
                bf[nt2 * 2 + 1][0] = t1; bf[nt2 * 2 + 1][1] = t3;
            }
            #pragma unroll
            for (int mt = 0; mt < 2; ++mt)
                #pragma unroll
                for (int nt = 0; nt < 8; ++nt)
                    mma16816(acc[mt][nt], af[mt], bf[nt]);
        }

        if (kt + 1 < NT) {
            const int nxt = cur ^ 1;
            *(uint4*)&As[nxt][r0g * PITCH + c0g] = ra0;
            *(uint4*)&As[nxt][r1g * PITCH + c0g] = ra1;
            *(uint4*)&Bs[nxt][r0g * PITCH + c0g] = rb0;
            *(uint4*)&Bs[nxt][r1g * PITCH + c0g] = rb1;
        }
        __syncthreads();
    }

    // epilogue: add bias, write C
    const int g = lane >> 2;
    const int tig = lane & 3;
    #pragma unroll
    for (int mt = 0; mt < 2; ++mt) {
        #pragma unroll
        for (int nt = 0; nt < 8; ++nt) {
            int n = n0 + noff + nt * 8 + tig * 2;
            float b0v = bias[n], b1v = bias[n + 1];
            int mA = m0 + moff + mt * 16 + g;
            float2 v0 = { acc[mt][nt][0] + b0v, acc[mt][nt][1] + b1v };
            float2 v1 = { acc[mt][nt][2] + b0v, acc[mt][nt][3] + b1v };
            *(float2*)(C + (size_t)mA * N + n) = v0;
            *(float2*)(C + (size_t)(mA + 8) * N + n) = v1;
        }
    }
}

// ---------------- grid barrier ----------------
__device__ __forceinline__ void grid_sync(unsigned* cnt, unsigned* gen, unsigned& local) {
    __syncthreads();
    if (threadIdx.x == 0) {
        __threadfence();
        if (atomicAdd(cnt, 1u) == NBLK - 1u) {
            atomicExch(cnt, 0u);
            __threadfence();
            atomicAdd(gen, 1u);
        } else {
            while (atomicAdd(gen, 0u) == local) { }
        }
        __threadfence();
    }
    __syncthreads();
    local++;
}

__device__ __forceinline__ float sigf(float x) { return 1.f / (1.f + expf(-x)); }

// ---------------- persistent LSTM layer 1 (H=256) ----------------
__global__ __launch_bounds__(256) void lstm_layer1(
    const float* __restrict__ pre, const float* __restrict__ Whh, float* __restrict__ y1)
{
    extern __shared__ float smemf[];
    float* Wst = smemf;
    float* hs  = smemf + H1 * 8;

    const int tid = threadIdx.x;
    const int bid = blockIdx.x;
    const int b   = tid & 127;
    const int jj  = tid >> 7;
    const int j   = bid * 2 + jj;

    #pragma unroll
    for (int r = 0; r < 8; ++r) {
        int jj2 = r >> 2, g = r & 3;
        const float* wrow = Whh + ((size_t)(g * H1 + bid * 2 + jj2)) * H1;
        for (int k = tid; k < H1; k += 256) Wst[k * 8 + jj2 * 4 + g] = wrow[k];
    }

    __shared__ unsigned s_gen;
    if (tid == 0) s_gen = atomicAdd(&g_gen1, 0u);
    __syncthreads();
    unsigned local = s_gen;

    float c0 = 0.f;

    for (int t = 0; t < T_STEPS; ++t) {
        float a0 = 0.f, a1 = 0.f, a2 = 0.f, a3 = 0.f;
        if (t > 0) {
            const float* hprev = g_h1[(t - 1) & 1];
            for (int k0 = 0; k0 < H1; k0 += 64) {
                const float4* src = (const float4*)(hprev + k0 * BATCH);
                float4* dst = (float4*)hs;
                #pragma unroll
                for (int i = tid; i < 64 * BATCH / 4; i += 256) dst[i] = src[i];
                __syncthreads();
                #pragma unroll 8
                for (int kk = 0; kk < 64; ++kk) {
                    float hv = hs[kk * BATCH + b];
                    float4 w = *(const float4*)(Wst + (size_t)(k0 + kk) * 8 + jj * 4);
                    a0 += w.x * hv; a1 += w.y * hv; a2 += w.z * hv; a3 += w.w * hv;
                }
                __syncthreads();
            }
        }
        const float* p = pre + ((size_t)t * BATCH + b) * (4 * H1);
        float ig = a0 + p[j];
        float fg = a1 + p[H1 + j];
        float gg = a2 + p[2 * H1 + j];
        float og = a3 + p[3 * H1 + j];
        c0 = sigf(fg) * c0 + sigf(ig) * tanhf(gg);
        float h2 = sigf(og) * tanhf(c0);
        y1[((size_t)t * BATCH + b) * H1 + j] = h2;
        if (t < T_STEPS - 1) {
            g_h1[t & 1][j * BATCH + b] = h2;
            grid_sync(&g_cnt1, &g_gen1, local);
        }
    }
}

// ---------------- persistent LSTM layer 2 (H=512) ----------------
__global__ __launch_bounds__(256) void lstm_layer2(
    const float* __restrict__ pre, const float* __restrict__ Whh, float* __restrict__ out)
{
    extern __shared__ float smemf[];
    float* Wst = smemf;
    float* hs  = smemf + H2 * 16;

    const int tid = threadIdx.x;
    const int bid = blockIdx.x;
    const int b   = tid & 127;
    const int jp  = tid >> 7;

    #pragma unroll
    for (int r = 0; r < 16; ++r) {
        int jj = r >> 2, g = r & 3;
        const float* wrow = Whh + ((size_t)(g * H2 + bid * 4 + jj)) * H2;
        for (int k = tid; k < H2; k += 256) Wst[k * 16 + jj * 4 + g] = wrow[k];
    }

    __shared__ unsigned s_gen;
    if (tid == 0) s_gen = atomicAdd(&g_gen2, 0u);
    __syncthreads();
    unsigned local = s_gen;

    float c0 = 0.f, c1 = 0.f;

    for (int t = 0; t < T_STEPS; ++t) {
        float acc[8];
        #pragma unroll
        for (int i = 0; i < 8; ++i) acc[i] = 0.f;

        if (t > 0) {
            const float* hprev = g_h2[(t - 1) & 1];
            for (int k0 = 0; k0 < H2; k0 += 64) {
                const float4* src = (const float4*)(hprev + k0 * BATCH);
                float4* dst = (float4*)hs;
                #pragma unroll
                for (int i = tid; i < 64 * BATCH / 4; i += 256) dst[i] = src[i];
                __syncthreads();
                #pragma unroll 4
                for (int kk = 0; kk < 64; ++kk) {
                    float hv = hs[kk * BATCH + b];
                    const float* wp = Wst + (size_t)(k0 + kk) * 16 + jp * 8;
                    float4 wa = *(const float4*)(wp);
                    float4 wb = *(const float4*)(wp + 4);
                    acc[0] += wa.x * hv; acc[1] += wa.y * hv;
                    acc[2] += wa.z * hv; acc[3] += wa.w * hv;
                    acc[4] += wb.x * hv; acc[5] += wb.y * hv;
                    acc[6] += wb.z * hv; acc[7] += wb.w * hv;
                }
                __syncthreads();
            }
        }

        const float* p = pre + ((size_t)t * BATCH + b) * (4 * H2);
        #pragma unroll
        for (int u = 0; u < 2; ++u) {
            int j = bid * 4 + jp * 2 + u;
            float ig = acc[u * 4 + 0] + p[j];
            float fg = acc[u * 4 + 1] + p[H2 + j];
            float gg = acc[u * 4 + 2] + p[2 * H2 + j];
            float og = acc[u * 4 + 3] + p[3 * H2 + j];
            float c = (u == 0) ? c0 : c1;
            c = sigf(fg) * c + sigf(ig) * tanhf(gg);
            if (u == 0) c0 = c; else c1 = c;
            float h2 = sigf(og) * tanhf(c);
            out[((size_t)t * BATCH + b) * H2 + j] = h2;
            if (t < T_STEPS - 1) g_h2[t & 1][j * BATCH + b] = h2;
        }
        if (t < T_STEPS - 1) grid_sync(&g_cnt2, &g_gen2, local);
    }
}

// ---------------- launch ----------------
extern "C" void kernel_launch(void* const* d_in, const int* in_sizes, int n_in,
                              void* d_out, int out_size)
{
    const float* inp  = (const float*)d_in[0];
    const float* Wih1 = (const float*)d_in[1];
    const float* Whh1 = (const float*)d_in[2];
    const float* b1   = (const float*)d_in[3];
    const float* Wih2 = (const float*)d_in[4];
    const float* Whh2 = (const float*)d_in[5];
    const float* b2   = (const float*)d_in[6];
    float* out = (float*)d_out;

    float *pre1, *y1, *pre2;
    __nv_bfloat16 *A1s, *W1s, *y1s, *W2s;
    cudaGetSymbolAddress((void**)&pre1, g_pre1);
    cudaGetSymbolAddress((void**)&y1,   g_y1);
    cudaGetSymbolAddress((void**)&pre2, g_pre2);
    cudaGetSymbolAddress((void**)&A1s,  g_A1s);
    cudaGetSymbolAddress((void**)&W1s,  g_W1s);
    cudaGetSymbolAddress((void**)&y1s,  g_y1s);
    cudaGetSymbolAddress((void**)&W2s,  g_W2s);

    const int smem1 = (H1 * 8 + 64 * BATCH) * sizeof(float);
    const int smem2 = (H2 * 16 + 64 * BATCH) * sizeof(float);
    cudaFuncSetAttribute(lstm_layer2, cudaFuncAttributeMaxDynamicSharedMemorySize, smem2);

    // ---- layer 1 ----
    split_bf16<<<dim3(IN_DIM / 1024, M_ROWS), 256>>>(inp, A1s, IN_DIM, 1);
    split_bf16<<<dim3(IN_DIM / 1024, 4 * H1), 256>>>(Wih1, W1s, IN_DIM, 0);
    gemm_hmma<<<dim3(4 * H1 / 128, M_ROWS / 128), 256>>>(
        A1s, W1s, b1, pre1, 4 * H1, 3 * IN_DIM);

    lstm_layer1<<<NBLK, 256, smem1>>>(pre1, Whh1, y1);

    // ---- layer 2 ----
    split_bf16<<<dim3(1, M_ROWS), 256>>>(y1, y1s, H1, 1);
    split_bf16<<<dim3(1, 4 * H2), 256>>>(Wih2, W2s, H1, 0);
    gemm_hmma<<<dim3(4 * H2 / 128, M_ROWS / 128), 256>>>(
        y1s, W2s, b2, pre2, 4 * H2, 3 * H1);

    lstm_layer2<<<NBLK, 256, smem2>>>(pre2, Whh2, out);
}